// round 10
// baseline (speedup 1.0000x reference)
#include <cuda_runtime.h>
#include <cuda_bf16.h>
#include <cstdint>

#define BQ 4
#define NN 4096
#define DM 512
#define LP 4104   // ceil(4096/12)*12
#define NROWS (BQ*LP)
#define NSPLIT 8
#define LQS (LP/NSPLIT)   // 513 keys per split
#define HQ (LP/2)         // 2052

// ---------------- scratch (device globals) ----------------
__device__ __nv_bfloat16 g_Yh[(size_t)BQ*NN*DM];   // conv output hi
__device__ __nv_bfloat16 g_Yl[(size_t)BQ*NN*DM];   // conv output lo
__device__ __nv_bfloat16 g_Wh[DM*DM];              // pw_w hi
__device__ __nv_bfloat16 g_Wl[DM*DM];              // pw_w lo
__device__ float g_Y2[(size_t)BQ*LP*DM];           // pointwise output
__device__ float g_T [NROWS];                      // per-position score dot (atomic)
__device__ float4 g_Pa[NSPLIT][NROWS];             // attention partial numerators
__device__ float  g_Pz[NSPLIT][NROWS];             // attention partial denominators

// ---------------- f32x2 packed helpers ----------------
__device__ __forceinline__ unsigned long long mul2(unsigned long long a, unsigned long long b) {
    unsigned long long d;
    asm("mul.rn.f32x2 %0, %1, %2;" : "=l"(d) : "l"(a), "l"(b));
    return d;
}
__device__ __forceinline__ unsigned long long fma2(unsigned long long a, unsigned long long b,
                                                   unsigned long long c) {
    unsigned long long d;
    asm("fma.rn.f32x2 %0, %1, %2, %3;" : "=l"(d) : "l"(a), "l"(b), "l"(c));
    return d;
}
__device__ __forceinline__ unsigned long long pack2(float lo, float hi) {
    unsigned long long d;
    asm("mov.b64 %0, {%1, %2};" : "=l"(d) : "f"(lo), "f"(hi));
    return d;
}
__device__ __forceinline__ void unpack2(unsigned long long v, float& lo, float& hi) {
    asm("mov.b64 {%0, %1}, %2;" : "=f"(lo), "=f"(hi) : "l"(v));
}

// ---------------- block-score softmax from T ----------------
__device__ __forceinline__ float4 score4_g(const float* __restrict__ Tb, int l) {
    float v0 = Tb[l];
    int j2 = l & ~1;
    float v1 = (Tb[j2] + Tb[j2 + 1]) * 0.5f;
    int j3 = (l / 3) * 3;
    float v2 = (Tb[j3] + Tb[j3 + 1] + Tb[j3 + 2]) * (1.0f / 3.0f);
    int j4 = l & ~3;
    float v3 = (Tb[j4] + Tb[j4 + 1] + Tb[j4 + 2] + Tb[j4 + 3]) * 0.25f;
    float mx = fmaxf(fmaxf(v0, v1), fmaxf(v2, v3));
    float e0 = __expf(v0 - mx), e1 = __expf(v1 - mx);
    float e2 = __expf(v2 - mx), e3 = __expf(v3 - mx);
    float inv = 1.0f / (e0 + e1 + e2 + e3);
    return make_float4(e0 * inv, e1 * inv, e2 * inv, e3 * inv);
}

// ---------------- conv (+ fused prep: W split, T zero, Y2 pad zero) ----------------
__global__ void __launch_bounds__(128) k_conv(const int* __restrict__ x,
                                              const float* __restrict__ emb,
                                              const float* __restrict__ dww,
                                              const float* __restrict__ dwb,
                                              const float* __restrict__ W) {
    // fused prep: 2048 blocks * 128 threads = 262144 = DM*DM exactly
    int gidx = (blockIdx.y * gridDim.x + blockIdx.x) * 128 + threadIdx.x;
    {
        float w = W[gidx];
        __nv_bfloat16 h = __float2bfloat16(w);
        g_Wh[gidx] = h;
        g_Wl[gidx] = __float2bfloat16(w - __bfloat162float(h));
    }
    if (gidx < NROWS) g_T[gidx] = 0.0f;
    if (gidx < BQ * 8 * DM) {
        int bb = gidx / (8 * DM);
        int r = gidx % (8 * DM);
        g_Y2[((size_t)bb * LP + NN + r / DM) * DM + (r % DM)] = 0.0f;
    }

    __shared__ float sE[11][DM];     // rows t0 .. t0+10 (22.5 KB)
    int t0 = blockIdx.x * 8;
    int b = blockIdx.y;
    int tid = threadIdx.x;

    for (int v = tid; v < 11 * 128; v += 128) {
        int r = v >> 7;
        int c4 = (v & 127) * 4;
        int t = t0 + r;
        float4 e = {0.f, 0.f, 0.f, 0.f};
        if (t < NN) {
            int id = x[b * NN + t];
            e = *(const float4*)(emb + (size_t)id * DM + c4);
        }
        *(float4*)(&sE[r][c4]) = e;
    }
    __syncthreads();

    int d0 = tid * 4;
    float w[4][4];
#pragma unroll
    for (int j = 0; j < 4; j++) {
        float4 wv = *(const float4*)(dww + (d0 + j) * 4);
        w[j][0] = wv.x; w[j][1] = wv.y; w[j][2] = wv.z; w[j][3] = wv.w;
    }
    float4 bb = *(const float4*)(dwb + d0);

#pragma unroll
    for (int tok = 0; tok < 8; tok++) {
        float acc[4] = {bb.x, bb.y, bb.z, bb.w};
#pragma unroll
        for (int k = 0; k < 4; k++) {
            float4 e = *(const float4*)(&sE[tok + k][d0]);
            acc[0] += e.x * w[0][k];
            acc[1] += e.y * w[1][k];
            acc[2] += e.z * w[2][k];
            acc[3] += e.w * w[3][k];
        }
        size_t base = ((size_t)(b * NN + t0 + tok)) * DM + d0;
        __nv_bfloat16 h[4], l[4];
#pragma unroll
        for (int j = 0; j < 4; j++) {
            h[j] = __float2bfloat16(acc[j]);
            l[j] = __float2bfloat16(acc[j] - __bfloat162float(h[j]));
        }
        __nv_bfloat162* ph = (__nv_bfloat162*)(g_Yh + base);
        __nv_bfloat162* pl = (__nv_bfloat162*)(g_Yl + base);
        ph[0] = __halves2bfloat162(h[0], h[1]);
        ph[1] = __halves2bfloat162(h[2], h[3]);
        pl[0] = __halves2bfloat162(l[0], l[1]);
        pl[1] = __halves2bfloat162(l[2], l[3]);
    }
}

// ---------------- HMMA GEMM: Y2 = Y @ W^T + bias, bf16x3, cp.async 3-stage ----------------
#define TILE_B 8192          // 128 rows * 64 B
#define STAGE_B (4*TILE_B)   // Ah, Al, Bh, Bl = 32768
#define GEMM_SMEM (3*STAGE_B)  // 98304

__device__ __forceinline__ uint32_t swz(uint32_t row, uint32_t chunk) {
    return row * 64 + ((chunk ^ ((row >> 1) & 3)) << 4);
}
__device__ __forceinline__ void ldsm4(uint32_t* r, uint32_t addr) {
    asm volatile("ldmatrix.sync.aligned.m8n8.x4.shared.b16 {%0,%1,%2,%3}, [%4];"
                 : "=r"(r[0]), "=r"(r[1]), "=r"(r[2]), "=r"(r[3]) : "r"(addr));
}
__device__ __forceinline__ void mma16816(float* c, const uint32_t* a, const uint32_t* b) {
    asm volatile(
        "mma.sync.aligned.m16n8k16.row.col.f32.bf16.bf16.f32 "
        "{%0,%1,%2,%3}, {%4,%5,%6,%7}, {%8,%9}, {%0,%1,%2,%3};"
        : "+f"(c[0]), "+f"(c[1]), "+f"(c[2]), "+f"(c[3])
        : "r"(a[0]), "r"(a[1]), "r"(a[2]), "r"(a[3]), "r"(b[0]), "r"(b[1]));
}
__device__ __forceinline__ void cpa16(uint32_t dst, const void* src) {
    asm volatile("cp.async.cg.shared.global [%0], [%1], 16;" :: "r"(dst), "l"(src));
}

__global__ void __launch_bounds__(256, 2) k_gemm_mma(const float* __restrict__ bias,
                                                     const float* __restrict__ sw) {
    extern __shared__ char sm[];
    uint32_t smu = (uint32_t)__cvta_generic_to_shared(sm);

    int tid = threadIdx.x, wid = tid >> 5, lane = tid & 31;
    int warp_m = wid & 1;
    int warp_n = wid >> 1;
    int mtile = blockIdx.x;
    int bn = blockIdx.y;

    const __nv_bfloat16* gA[2] = {g_Yh + (size_t)mtile * 128 * DM,
                                  g_Yl + (size_t)mtile * 128 * DM};
    const __nv_bfloat16* gB[2] = {g_Wh + (size_t)bn * 128 * DM,
                                  g_Wl + (size_t)bn * 128 * DM};

    int r0 = tid >> 2, cc0 = tid & 3;
    int r1 = r0 + 64;
    uint32_t so0 = swz(r0, cc0);
    uint32_t so1 = swz(r1, cc0);

    auto load_stage = [&](int kc, int stage) {
        uint32_t base = smu + stage * STAGE_B;
        size_t go0 = (size_t)r0 * DM + kc * 32 + cc0 * 8;
        size_t go1 = (size_t)r1 * DM + kc * 32 + cc0 * 8;
#pragma unroll
        for (int p = 0; p < 2; p++) {
            cpa16(base + p * TILE_B + so0, gA[p] + go0);
            cpa16(base + p * TILE_B + so1, gA[p] + go1);
            cpa16(base + (2 + p) * TILE_B + so0, gB[p] + go0);
            cpa16(base + (2 + p) * TILE_B + so1, gB[p] + go1);
        }
        asm volatile("cp.async.commit_group;");
    };

    float c[4][4][4];
#pragma unroll
    for (int mt = 0; mt < 4; mt++)
#pragma unroll
        for (int nt = 0; nt < 4; nt++)
#pragma unroll
            for (int e = 0; e < 4; e++) c[mt][nt][e] = 0.0f;

    int lr = lane & 7, g = lane >> 3;
    int a_row = (g & 1) * 8 + lr;
    int a_kc8 = (g >> 1);
    int b_nrw = (g >> 1) * 8 + lr;
    int b_kc8 = (g & 1);

    load_stage(0, 0);
    load_stage(1, 1);

    for (int kc = 0; kc < 16; kc++) {
        if (kc + 1 < 16) asm volatile("cp.async.wait_group 1;");
        else             asm volatile("cp.async.wait_group 0;");
        __syncthreads();
        if (kc + 2 < 16) load_stage(kc + 2, (kc + 2) % 3);

        uint32_t sAh = smu + (kc % 3) * STAGE_B;
        uint32_t sAl = sAh + TILE_B;
        uint32_t sBh = sAh + 2 * TILE_B;
        uint32_t sBl = sAh + 3 * TILE_B;

#pragma unroll
        for (int ks = 0; ks < 2; ks++) {
            uint32_t bh[8], bl[8], a[4][4];
#pragma unroll
            for (int hh = 0; hh < 2; hh++) {
                uint32_t row = warp_n * 32 + hh * 16 + b_nrw;
                uint32_t off = swz(row, 2 * ks + b_kc8);
                ldsm4(bh + hh * 4, sBh + off);
                ldsm4(bl + hh * 4, sBl + off);
            }
#pragma unroll
            for (int mt = 0; mt < 4; mt++) {
                uint32_t row = warp_m * 64 + mt * 16 + a_row;
                uint32_t off = swz(row, 2 * ks + a_kc8);
                ldsm4(a[mt], sAh + off);
            }
#pragma unroll
            for (int mt = 0; mt < 4; mt++)
#pragma unroll
                for (int nt = 0; nt < 4; nt++) {
                    int bi = (nt >> 1) * 4 + (nt & 1) * 2;
                    uint32_t b0[2] = {bh[bi], bh[bi + 1]};
                    mma16816(c[mt][nt], a[mt], b0);
                    uint32_t b1[2] = {bl[bi], bl[bi + 1]};
                    mma16816(c[mt][nt], a[mt], b1);
                }
#pragma unroll
            for (int mt = 0; mt < 4; mt++) {
                uint32_t row = warp_m * 64 + mt * 16 + a_row;
                uint32_t off = swz(row, 2 * ks + a_kc8);
                ldsm4(a[mt], sAl + off);
            }
#pragma unroll
            for (int mt = 0; mt < 4; mt++)
#pragma unroll
                for (int nt = 0; nt < 4; nt++) {
                    int bi = (nt >> 1) * 4 + (nt & 1) * 2;
                    uint32_t b0[2] = {bh[bi], bh[bi + 1]};
                    mma16816(c[mt][nt], a[mt], b0);
                }
        }
    }

    float tp[4][2];
#pragma unroll
    for (int mt = 0; mt < 4; mt++) { tp[mt][0] = 0.0f; tp[mt][1] = 0.0f; }

#pragma unroll
    for (int mt = 0; mt < 4; mt++) {
        int row0 = mtile * 128 + warp_m * 64 + mt * 16 + (lane >> 2);
        int row1 = row0 + 8;
        int b0i = row0 >> 12, l0i = row0 & 4095;
        int b1i = row1 >> 12, l1i = row1 & 4095;
        float* o0 = g_Y2 + ((size_t)b0i * LP + l0i) * DM;
        float* o1 = g_Y2 + ((size_t)b1i * LP + l1i) * DM;
#pragma unroll
        for (int nt = 0; nt < 4; nt++) {
            int col = bn * 128 + warp_n * 32 + nt * 8 + 2 * (lane & 3);
            float bi0 = bias[col], bi1 = bias[col + 1];
            float s0 = sw[col], s1 = sw[col + 1];
            float v00 = c[mt][nt][0] + bi0, v01 = c[mt][nt][1] + bi1;
            float v10 = c[mt][nt][2] + bi0, v11 = c[mt][nt][3] + bi1;
            tp[mt][0] += v00 * s0 + v01 * s1;
            tp[mt][1] += v10 * s0 + v11 * s1;
            float2 w0 = {v00, v01}, w1 = {v10, v11};
            *(float2*)(o0 + col) = w0;
            *(float2*)(o1 + col) = w1;
        }
    }
#pragma unroll
    for (int mt = 0; mt < 4; mt++) {
#pragma unroll
        for (int rs = 0; rs < 2; rs++) {
            float r = tp[mt][rs];
            r += __shfl_xor_sync(0xffffffff, r, 1);
            r += __shfl_xor_sync(0xffffffff, r, 2);
            if ((lane & 3) == 0) {
                int row = mtile * 128 + warp_m * 64 + mt * 16 + rs * 8 + (lane >> 2);
                int bb = row >> 12, ll = row & 4095;
                atomicAdd(&g_T[bb * LP + ll], r);
            }
        }
    }
}

// ---------------- attention (+ fused block-score softmax), 8-way key split ----------------
__global__ void __launch_bounds__(128) k_attn_part() {
    __shared__ float4 sS[LQS];       // key scores (8.2 KB)
    __shared__ float sT[LQS + 8];    // T window with +-3 halo
    int b = blockIdx.y, sp = blockIdx.z;
    const float* Tb = g_T + (size_t)b * LP;
    int s0 = sp * LQS;
    int w0 = s0 - 3;
    int wlen = LQS + 6;

    for (int j = threadIdx.x; j < wlen; j += 128) {
        int t = w0 + j;
        sT[j] = (t >= 0 && t < LP) ? Tb[t] : 0.0f;
    }
    __syncthreads();

    // key scores from the smem T window (same math as the old k_scores)
    for (int j = threadIdx.x; j < LQS; j += 128) {
        int l = s0 + j;
        float v0 = sT[l - w0];
        int j2 = l & ~1;
        float v1 = (sT[j2 - w0] + sT[j2 + 1 - w0]) * 0.5f;
        int j3 = (l / 3) * 3;
        float v2 = (sT[j3 - w0] + sT[j3 + 1 - w0] + sT[j3 + 2 - w0]) * (1.0f / 3.0f);
        int j4 = l & ~3;
        float v3 = (sT[j4 - w0] + sT[j4 + 1 - w0] + sT[j4 + 2 - w0] + sT[j4 + 3 - w0]) * 0.25f;
        float mx = fmaxf(fmaxf(v0, v1), fmaxf(v2, v3));
        float e0 = __expf(v0 - mx), e1 = __expf(v1 - mx);
        float e2 = __expf(v2 - mx), e3 = __expf(v3 - mx);
        float inv = 1.0f / (e0 + e1 + e2 + e3);
        sS[j] = make_float4(e0 * inv, e1 * inv, e2 * inv, e3 * inv);
    }
    __syncthreads();

    int i0 = blockIdx.x * 128 + threadIdx.x;
    if (i0 >= HQ) return;
    int i1 = i0 + HQ;

    const float L2E = 1.4426950408889634f;
    float4 q0 = score4_g(Tb, i0);
    float4 q1 = score4_g(Tb, i1);
    unsigned long long q0a = pack2(q0.x * L2E, q0.y * L2E);
    unsigned long long q0b = pack2(q0.z * L2E, q0.w * L2E);
    unsigned long long q1a = pack2(q1.x * L2E, q1.y * L2E);
    unsigned long long q1b = pack2(q1.z * L2E, q1.w * L2E);

    unsigned long long A0a = 0, A0b = 0, A1a = 0, A1b = 0;
    float z0 = 0.0f, z1 = 0.0f;

    const ulonglong2* sSv = (const ulonglong2*)sS;
#pragma unroll 4
    for (int j = 0; j < LQS; j++) {
        ulonglong2 sv = sSv[j];
        unsigned long long d0p = fma2(q0b, sv.y, mul2(q0a, sv.x));
        float d0l, d0h; unpack2(d0p, d0l, d0h);
        float e0;
        asm("ex2.approx.f32 %0, %1;" : "=f"(e0) : "f"(d0l + d0h));
        unsigned long long e0p = pack2(e0, e0);
        A0a = fma2(e0p, sv.x, A0a);
        A0b = fma2(e0p, sv.y, A0b);
        z0 += e0;
        unsigned long long d1p = fma2(q1b, sv.y, mul2(q1a, sv.x));
        float d1l, d1h; unpack2(d1p, d1l, d1h);
        float e1;
        asm("ex2.approx.f32 %0, %1;" : "=f"(e1) : "f"(d1l + d1h));
        unsigned long long e1p = pack2(e1, e1);
        A1a = fma2(e1p, sv.x, A1a);
        A1b = fma2(e1p, sv.y, A1b);
        z1 += e1;
    }

    float4 r0, r1;
    unpack2(A0a, r0.x, r0.y); unpack2(A0b, r0.z, r0.w);
    unpack2(A1a, r1.x, r1.y); unpack2(A1b, r1.z, r1.w);
    int row0 = b * LP + i0, row1 = b * LP + i1;
    g_Pa[sp][row0] = r0;  g_Pz[sp][row0] = z0;
    g_Pa[sp][row1] = r1;  g_Pz[sp][row1] = z1;
}

// ---------------- output: fused split-reduction + weighted pooling + DS mean ----------------
__global__ void __launch_bounds__(128) k_out(float* __restrict__ out) {
    __shared__ float4 s2s[4];
    int g = blockIdx.x;
    int b = blockIdx.y;
    int base = 4 * g - 2;
    int tid = threadIdx.x;

    if (tid < 4) {
        int row = b * LP + 4 * g + tid;
        float z = 0.0f;
        float4 a = make_float4(0.0f, 0.0f, 0.0f, 0.0f);
#pragma unroll
        for (int s = 0; s < NSPLIT; s++) {
            float4 p = g_Pa[s][row];
            a.x += p.x; a.y += p.y; a.z += p.z; a.w += p.w;
            z += g_Pz[s][row];
        }
        float inv = 1.0f / z;
        s2s[tid] = make_float4(a.x * inv, a.y * inv, a.z * inv, a.w * inv);
    }
    __syncthreads();

    float w[8];
#pragma unroll
    for (int r = 0; r < 8; r++) w[r] = 0.0f;

#pragma unroll
    for (int lo = 0; lo < 4; lo++) {
        int l = 4 * g + lo;
        float4 s2 = s2s[lo];
        w[l - base] += s2.x * 0.25f;
        { int j0 = l & ~1;      float c = s2.y * (0.25f * 0.5f);
          w[j0 - base] += c; w[j0 + 1 - base] += c; }
        { int j0 = (l / 3) * 3; float c = s2.z * (0.25f / 3.0f);
          w[j0 - base] += c; w[j0 + 1 - base] += c; w[j0 + 2 - base] += c; }
        { int j0 = l & ~3;      float c = s2.w * (0.25f * 0.25f);
          w[j0 - base] += c; w[j0 + 1 - base] += c;
          w[j0 + 2 - base] += c; w[j0 + 3 - base] += c; }
    }

    int d = tid * 4;
    float4 acc = {0.0f, 0.0f, 0.0f, 0.0f};
#pragma unroll
    for (int r = 0; r < 8; r++) {
        int row = base + r;
        float wr = w[r];
        if (row >= 0 && wr != 0.0f) {
            float4 v = *(const float4*)(g_Y2 + ((size_t)b * LP + row) * DM + d);
            acc.x += wr * v.x; acc.y += wr * v.y;
            acc.z += wr * v.z; acc.w += wr * v.w;
        }
    }
    *(float4*)(out + ((size_t)(b * 1024 + g)) * DM + d) = acc;
}

// ---------------- launcher ----------------
extern "C" void kernel_launch(void* const* d_in, const int* in_sizes, int n_in,
                              void* d_out, int out_size) {
    const int*   x   = (const int*)  d_in[0];
    const float* emb = (const float*)d_in[1];
    const float* dww = (const float*)d_in[2];
    const float* dwb = (const float*)d_in[3];
    const float* pww = (const float*)d_in[4];
    const float* pwb = (const float*)d_in[5];
    const float* sw  = (const float*)d_in[6];
    const float* sb  = (const float*)d_in[7];
    float* out = (float*)d_out;

    cudaFuncSetAttribute(k_gemm_mma, cudaFuncAttributeMaxDynamicSharedMemorySize, GEMM_SMEM);

    k_conv<<<dim3(NN / 8, BQ), 128>>>(x, emb, dww, dwb, pww);
    k_gemm_mma<<<dim3(128, 4), 256, GEMM_SMEM>>>(pwb, sw);
    k_attn_part<<<dim3((HQ + 127) / 128, BQ, NSPLIT), 128>>>();
    k_out<<<dim3(1024, BQ), 128>>>(out);
}

// round 11
// speedup vs baseline: 1.0945x; 1.0945x over previous
#include <cuda_runtime.h>
#include <cuda_bf16.h>
#include <cstdint>

#define BQ 4
#define NN 4096
#define DM 512
#define LP 4104   // ceil(4096/12)*12
#define NROWS (BQ*LP)
#define NSPLIT 8
#define LQS (LP/NSPLIT)   // 513 keys per split
#define HQ (LP/2)         // 2052

// ---------------- scratch (device globals) ----------------
__device__ __nv_bfloat16 g_Yh[(size_t)BQ*NN*DM];   // conv output hi
__device__ __nv_bfloat16 g_Yl[(size_t)BQ*NN*DM];   // conv output lo
__device__ __nv_bfloat16 g_Wh[DM*DM];              // pw_w hi
__device__ __nv_bfloat16 g_Wl[DM*DM];              // pw_w lo
__device__ float g_Y2[(size_t)BQ*LP*DM];           // pointwise output
__device__ float g_T [NROWS];                      // per-position score dot (atomic)
__device__ float g_S [NROWS*4];                    // softmaxed block scores
__device__ float4 g_Pa[NSPLIT][NROWS];             // attention partial numerators
__device__ float  g_Pz[NSPLIT][NROWS];             // attention partial denominators

// ---------------- f32x2 packed helpers ----------------
__device__ __forceinline__ unsigned long long mul2(unsigned long long a, unsigned long long b) {
    unsigned long long d;
    asm("mul.rn.f32x2 %0, %1, %2;" : "=l"(d) : "l"(a), "l"(b));
    return d;
}
__device__ __forceinline__ unsigned long long fma2(unsigned long long a, unsigned long long b,
                                                   unsigned long long c) {
    unsigned long long d;
    asm("fma.rn.f32x2 %0, %1, %2, %3;" : "=l"(d) : "l"(a), "l"(b), "l"(c));
    return d;
}
__device__ __forceinline__ unsigned long long pack2(float lo, float hi) {
    unsigned long long d;
    asm("mov.b64 %0, {%1, %2};" : "=l"(d) : "f"(lo), "f"(hi));
    return d;
}
__device__ __forceinline__ void unpack2(unsigned long long v, float& lo, float& hi) {
    asm("mov.b64 {%0, %1}, %2;" : "=f"(lo), "=f"(hi) : "l"(v));
}

// ---------------- conv (+ fused prep: W split, T zero, Y2 pad zero) ----------------
__global__ void __launch_bounds__(128) k_conv(const int* __restrict__ x,
                                              const float* __restrict__ emb,
                                              const float* __restrict__ dww,
                                              const float* __restrict__ dwb,
                                              const float* __restrict__ W) {
    // fused prep: 2048 blocks * 128 threads = 262144 = DM*DM exactly
    int gidx = (blockIdx.y * gridDim.x + blockIdx.x) * 128 + threadIdx.x;
    {
        float w = W[gidx];
        __nv_bfloat16 h = __float2bfloat16(w);
        g_Wh[gidx] = h;
        g_Wl[gidx] = __float2bfloat16(w - __bfloat162float(h));
    }
    if (gidx < NROWS) g_T[gidx] = 0.0f;
    if (gidx < BQ * 8 * DM) {
        int bb = gidx / (8 * DM);
        int r = gidx % (8 * DM);
        g_Y2[((size_t)bb * LP + NN + r / DM) * DM + (r % DM)] = 0.0f;
    }

    __shared__ float sE[11][DM];     // rows t0 .. t0+10 (22.5 KB)
    int t0 = blockIdx.x * 8;
    int b = blockIdx.y;
    int tid = threadIdx.x;

    for (int v = tid; v < 11 * 128; v += 128) {
        int r = v >> 7;
        int c4 = (v & 127) * 4;
        int t = t0 + r;
        float4 e = {0.f, 0.f, 0.f, 0.f};
        if (t < NN) {
            int id = x[b * NN + t];
            e = *(const float4*)(emb + (size_t)id * DM + c4);
        }
        *(float4*)(&sE[r][c4]) = e;
    }
    __syncthreads();

    int d0 = tid * 4;
    float w[4][4];
#pragma unroll
    for (int j = 0; j < 4; j++) {
        float4 wv = *(const float4*)(dww + (d0 + j) * 4);
        w[j][0] = wv.x; w[j][1] = wv.y; w[j][2] = wv.z; w[j][3] = wv.w;
    }
    float4 bb = *(const float4*)(dwb + d0);

#pragma unroll
    for (int tok = 0; tok < 8; tok++) {
        float acc[4] = {bb.x, bb.y, bb.z, bb.w};
#pragma unroll
        for (int k = 0; k < 4; k++) {
            float4 e = *(const float4*)(&sE[tok + k][d0]);
            acc[0] += e.x * w[0][k];
            acc[1] += e.y * w[1][k];
            acc[2] += e.z * w[2][k];
            acc[3] += e.w * w[3][k];
        }
        size_t base = ((size_t)(b * NN + t0 + tok)) * DM + d0;
        __nv_bfloat16 h[4], l[4];
#pragma unroll
        for (int j = 0; j < 4; j++) {
            h[j] = __float2bfloat16(acc[j]);
            l[j] = __float2bfloat16(acc[j] - __bfloat162float(h[j]));
        }
        __nv_bfloat162* ph = (__nv_bfloat162*)(g_Yh + base);
        __nv_bfloat162* pl = (__nv_bfloat162*)(g_Yl + base);
        ph[0] = __halves2bfloat162(h[0], h[1]);
        ph[1] = __halves2bfloat162(h[2], h[3]);
        pl[0] = __halves2bfloat162(l[0], l[1]);
        pl[1] = __halves2bfloat162(l[2], l[3]);
    }
}

// ---------------- HMMA GEMM: Y2 = Y @ W^T + bias, bf16x3, cp.async 3-stage ----------------
#define TILE_B 8192          // 128 rows * 64 B
#define STAGE_B (4*TILE_B)   // Ah, Al, Bh, Bl = 32768
#define GEMM_SMEM (3*STAGE_B)  // 98304

__device__ __forceinline__ uint32_t swz(uint32_t row, uint32_t chunk) {
    return row * 64 + ((chunk ^ ((row >> 1) & 3)) << 4);
}
__device__ __forceinline__ void ldsm4(uint32_t* r, uint32_t addr) {
    asm volatile("ldmatrix.sync.aligned.m8n8.x4.shared.b16 {%0,%1,%2,%3}, [%4];"
                 : "=r"(r[0]), "=r"(r[1]), "=r"(r[2]), "=r"(r[3]) : "r"(addr));
}
__device__ __forceinline__ void mma16816(float* c, const uint32_t* a, const uint32_t* b) {
    asm volatile(
        "mma.sync.aligned.m16n8k16.row.col.f32.bf16.bf16.f32 "
        "{%0,%1,%2,%3}, {%4,%5,%6,%7}, {%8,%9}, {%0,%1,%2,%3};"
        : "+f"(c[0]), "+f"(c[1]), "+f"(c[2]), "+f"(c[3])
        : "r"(a[0]), "r"(a[1]), "r"(a[2]), "r"(a[3]), "r"(b[0]), "r"(b[1]));
}
__device__ __forceinline__ void cpa16(uint32_t dst, const void* src) {
    asm volatile("cp.async.cg.shared.global [%0], [%1], 16;" :: "r"(dst), "l"(src));
}

__global__ void __launch_bounds__(256, 2) k_gemm_mma(const float* __restrict__ bias,
                                                     const float* __restrict__ sw) {
    extern __shared__ char sm[];
    uint32_t smu = (uint32_t)__cvta_generic_to_shared(sm);

    int tid = threadIdx.x, wid = tid >> 5, lane = tid & 31;
    int warp_m = wid & 1;
    int warp_n = wid >> 1;
    int mtile = blockIdx.x;
    int bn = blockIdx.y;

    const __nv_bfloat16* gA[2] = {g_Yh + (size_t)mtile * 128 * DM,
                                  g_Yl + (size_t)mtile * 128 * DM};
    const __nv_bfloat16* gB[2] = {g_Wh + (size_t)bn * 128 * DM,
                                  g_Wl + (size_t)bn * 128 * DM};

    int r0 = tid >> 2, cc0 = tid & 3;
    int r1 = r0 + 64;
    uint32_t so0 = swz(r0, cc0);
    uint32_t so1 = swz(r1, cc0);

    auto load_stage = [&](int kc, int stage) {
        uint32_t base = smu + stage * STAGE_B;
        size_t go0 = (size_t)r0 * DM + kc * 32 + cc0 * 8;
        size_t go1 = (size_t)r1 * DM + kc * 32 + cc0 * 8;
#pragma unroll
        for (int p = 0; p < 2; p++) {
            cpa16(base + p * TILE_B + so0, gA[p] + go0);
            cpa16(base + p * TILE_B + so1, gA[p] + go1);
            cpa16(base + (2 + p) * TILE_B + so0, gB[p] + go0);
            cpa16(base + (2 + p) * TILE_B + so1, gB[p] + go1);
        }
        asm volatile("cp.async.commit_group;");
    };

    float c[4][4][4];
#pragma unroll
    for (int mt = 0; mt < 4; mt++)
#pragma unroll
        for (int nt = 0; nt < 4; nt++)
#pragma unroll
            for (int e = 0; e < 4; e++) c[mt][nt][e] = 0.0f;

    int lr = lane & 7, g = lane >> 3;
    int a_row = (g & 1) * 8 + lr;
    int a_kc8 = (g >> 1);
    int b_nrw = (g >> 1) * 8 + lr;
    int b_kc8 = (g & 1);

    load_stage(0, 0);
    load_stage(1, 1);

    for (int kc = 0; kc < 16; kc++) {
        if (kc + 1 < 16) asm volatile("cp.async.wait_group 1;");
        else             asm volatile("cp.async.wait_group 0;");
        __syncthreads();
        if (kc + 2 < 16) load_stage(kc + 2, (kc + 2) % 3);

        uint32_t sAh = smu + (kc % 3) * STAGE_B;
        uint32_t sAl = sAh + TILE_B;
        uint32_t sBh = sAh + 2 * TILE_B;
        uint32_t sBl = sAh + 3 * TILE_B;

#pragma unroll
        for (int ks = 0; ks < 2; ks++) {
            uint32_t bh[8], bl[8], a[4][4];
#pragma unroll
            for (int hh = 0; hh < 2; hh++) {
                uint32_t row = warp_n * 32 + hh * 16 + b_nrw;
                uint32_t off = swz(row, 2 * ks + b_kc8);
                ldsm4(bh + hh * 4, sBh + off);
                ldsm4(bl + hh * 4, sBl + off);
            }
#pragma unroll
            for (int mt = 0; mt < 4; mt++) {
                uint32_t row = warp_m * 64 + mt * 16 + a_row;
                uint32_t off = swz(row, 2 * ks + a_kc8);
                ldsm4(a[mt], sAh + off);
            }
#pragma unroll
            for (int mt = 0; mt < 4; mt++)
#pragma unroll
                for (int nt = 0; nt < 4; nt++) {
                    int bi = (nt >> 1) * 4 + (nt & 1) * 2;
                    uint32_t b0[2] = {bh[bi], bh[bi + 1]};
                    mma16816(c[mt][nt], a[mt], b0);
                    uint32_t b1[2] = {bl[bi], bl[bi + 1]};
                    mma16816(c[mt][nt], a[mt], b1);
                }
#pragma unroll
            for (int mt = 0; mt < 4; mt++) {
                uint32_t row = warp_m * 64 + mt * 16 + a_row;
                uint32_t off = swz(row, 2 * ks + a_kc8);
                ldsm4(a[mt], sAl + off);
            }
#pragma unroll
            for (int mt = 0; mt < 4; mt++)
#pragma unroll
                for (int nt = 0; nt < 4; nt++) {
                    int bi = (nt >> 1) * 4 + (nt & 1) * 2;
                    uint32_t b0[2] = {bh[bi], bh[bi + 1]};
                    mma16816(c[mt][nt], a[mt], b0);
                }
        }
    }

    float tp[4][2];
#pragma unroll
    for (int mt = 0; mt < 4; mt++) { tp[mt][0] = 0.0f; tp[mt][1] = 0.0f; }

#pragma unroll
    for (int mt = 0; mt < 4; mt++) {
        int row0 = mtile * 128 + warp_m * 64 + mt * 16 + (lane >> 2);
        int row1 = row0 + 8;
        int b0i = row0 >> 12, l0i = row0 & 4095;
        int b1i = row1 >> 12, l1i = row1 & 4095;
        float* o0 = g_Y2 + ((size_t)b0i * LP + l0i) * DM;
        float* o1 = g_Y2 + ((size_t)b1i * LP + l1i) * DM;
#pragma unroll
        for (int nt = 0; nt < 4; nt++) {
            int col = bn * 128 + warp_n * 32 + nt * 8 + 2 * (lane & 3);
            float bi0 = bias[col], bi1 = bias[col + 1];
            float s0 = sw[col], s1 = sw[col + 1];
            float v00 = c[mt][nt][0] + bi0, v01 = c[mt][nt][1] + bi1;
            float v10 = c[mt][nt][2] + bi0, v11 = c[mt][nt][3] + bi1;
            tp[mt][0] += v00 * s0 + v01 * s1;
            tp[mt][1] += v10 * s0 + v11 * s1;
            float2 w0 = {v00, v01}, w1 = {v10, v11};
            *(float2*)(o0 + col) = w0;
            *(float2*)(o1 + col) = w1;
        }
    }
#pragma unroll
    for (int mt = 0; mt < 4; mt++) {
#pragma unroll
        for (int rs = 0; rs < 2; rs++) {
            float r = tp[mt][rs];
            r += __shfl_xor_sync(0xffffffff, r, 1);
            r += __shfl_xor_sync(0xffffffff, r, 2);
            if ((lane & 3) == 0) {
                int row = mtile * 128 + warp_m * 64 + mt * 16 + rs * 8 + (lane >> 2);
                int bb = row >> 12, ll = row & 4095;
                atomicAdd(&g_T[bb * LP + ll], r);
            }
        }
    }
}

// ---------------- block means of T + softmax over k ----------------
__global__ void __launch_bounds__(256) k_scores(const float* __restrict__ sb) {
    int idx = blockIdx.x * blockDim.x + threadIdx.x;
    if (idx >= NROWS) return;
    int b = idx / LP, l = idx % LP;
    const float* Tb = g_T + (size_t)b * LP;
    float v[4];
    v[0] = Tb[l];
    { int j = l & ~1;      v[1] = (Tb[j] + Tb[j + 1]) * 0.5f; }
    { int j = (l / 3) * 3; v[2] = (Tb[j] + Tb[j + 1] + Tb[j + 2]) * (1.0f / 3.0f); }
    { int j = l & ~3;      v[3] = (Tb[j] + Tb[j + 1] + Tb[j + 2] + Tb[j + 3]) * 0.25f; }
    float mx = v[0];
#pragma unroll
    for (int k = 1; k < 4; k++) mx = fmaxf(mx, v[k]);
    float e[4], z = 0.0f;
#pragma unroll
    for (int k = 0; k < 4; k++) { e[k] = __expf(v[k] - mx); z += e[k]; }
    float inv = 1.0f / z;
    float4 o = {e[0] * inv, e[1] * inv, e[2] * inv, e[3] * inv};
    *(float4*)(g_S + (size_t)idx * 4) = o;
}

// ---------------- score attention, 8-way key split, 2 queries/thread, f32x2 ----------------
__global__ void __launch_bounds__(128) k_attn_part() {
    __shared__ float4 sS[LQS];   // 513 keys = 8.2 KB
    int b = blockIdx.y, sp = blockIdx.z;
    const float4* Sb = (const float4*)(g_S + ((size_t)b * LP + sp * LQS) * 4);
    for (int j = threadIdx.x; j < LQS; j += 128) sS[j] = Sb[j];
    __syncthreads();

    int i0 = blockIdx.x * 128 + threadIdx.x;
    if (i0 >= HQ) return;
    int i1 = i0 + HQ;

    const float L2E = 1.4426950408889634f;
    float4 q0 = *(const float4*)(g_S + ((size_t)b * LP + i0) * 4);
    float4 q1 = *(const float4*)(g_S + ((size_t)b * LP + i1) * 4);
    unsigned long long q0a = pack2(q0.x * L2E, q0.y * L2E);
    unsigned long long q0b = pack2(q0.z * L2E, q0.w * L2E);
    unsigned long long q1a = pack2(q1.x * L2E, q1.y * L2E);
    unsigned long long q1b = pack2(q1.z * L2E, q1.w * L2E);

    unsigned long long A0a = 0, A0b = 0, A1a = 0, A1b = 0;
    float z0 = 0.0f, z1 = 0.0f;

    const ulonglong2* sSv = (const ulonglong2*)sS;
#pragma unroll 4
    for (int j = 0; j < LQS; j++) {
        ulonglong2 sv = sSv[j];
        unsigned long long d0p = fma2(q0b, sv.y, mul2(q0a, sv.x));
        float d0l, d0h; unpack2(d0p, d0l, d0h);
        float e0;
        asm("ex2.approx.f32 %0, %1;" : "=f"(e0) : "f"(d0l + d0h));
        unsigned long long e0p = pack2(e0, e0);
        A0a = fma2(e0p, sv.x, A0a);
        A0b = fma2(e0p, sv.y, A0b);
        z0 += e0;
        unsigned long long d1p = fma2(q1b, sv.y, mul2(q1a, sv.x));
        float d1l, d1h; unpack2(d1p, d1l, d1h);
        float e1;
        asm("ex2.approx.f32 %0, %1;" : "=f"(e1) : "f"(d1l + d1h));
        unsigned long long e1p = pack2(e1, e1);
        A1a = fma2(e1p, sv.x, A1a);
        A1b = fma2(e1p, sv.y, A1b);
        z1 += e1;
    }

    float4 r0, r1;
    unpack2(A0a, r0.x, r0.y); unpack2(A0b, r0.z, r0.w);
    unpack2(A1a, r1.x, r1.y); unpack2(A1b, r1.z, r1.w);
    int row0 = b * LP + i0, row1 = b * LP + i1;
    g_Pa[sp][row0] = r0;  g_Pz[sp][row0] = z0;
    g_Pa[sp][row1] = r1;  g_Pz[sp][row1] = z1;
}

// ---------------- output: split-reduce + one-thread weight build + pooled store ----------
__global__ void __launch_bounds__(128) k_out(float* __restrict__ out) {
    __shared__ float4 s2s[4];
    __shared__ float ws[8];
    int g = blockIdx.x;
    int b = blockIdx.y;
    int base = 4 * g - 2;
    int tid = threadIdx.x;

    if (tid < 4) {
        int row = b * LP + 4 * g + tid;
        float z = 0.0f;
        float4 a = make_float4(0.0f, 0.0f, 0.0f, 0.0f);
#pragma unroll
        for (int s = 0; s < NSPLIT; s++) {
            float4 p = g_Pa[s][row];
            a.x += p.x; a.y += p.y; a.z += p.z; a.w += p.w;
            z += g_Pz[s][row];
        }
        float inv = 1.0f / z;
        s2s[tid] = make_float4(a.x * inv, a.y * inv, a.z * inv, a.w * inv);
    }
    __syncthreads();

    if (tid == 0) {
        float w[8];
#pragma unroll
        for (int r = 0; r < 8; r++) w[r] = 0.0f;
#pragma unroll
        for (int lo = 0; lo < 4; lo++) {
            int l = 4 * g + lo;
            float4 s2 = s2s[lo];
            w[l - base] += s2.x * 0.25f;
            { int j0 = l & ~1;      float c = s2.y * (0.25f * 0.5f);
              w[j0 - base] += c; w[j0 + 1 - base] += c; }
            { int j0 = (l / 3) * 3; float c = s2.z * (0.25f / 3.0f);
              w[j0 - base] += c; w[j0 + 1 - base] += c; w[j0 + 2 - base] += c; }
            { int j0 = l & ~3;      float c = s2.w * (0.25f * 0.25f);
              w[j0 - base] += c; w[j0 + 1 - base] += c;
              w[j0 + 2 - base] += c; w[j0 + 3 - base] += c; }
        }
#pragma unroll
        for (int r = 0; r < 8; r++) ws[r] = w[r];
    }
    __syncthreads();

    int d = tid * 4;
    const float* Yb = g_Y2 + ((size_t)b * LP + base) * DM + d;
    float4 acc = {0.0f, 0.0f, 0.0f, 0.0f};
#pragma unroll
    for (int r = 0; r < 8; r++) {
        int row = base + r;
        float wr = ws[r];
        if (row >= 0 && wr != 0.0f) {
            float4 v = *(const float4*)(Yb + (size_t)r * DM);
            acc.x += wr * v.x; acc.y += wr * v.y;
            acc.z += wr * v.z; acc.w += wr * v.w;
        }
    }
    *(float4*)(out + ((size_t)(b * 1024 + g)) * DM + d) = acc;
}

// ---------------- launcher ----------------
extern "C" void kernel_launch(void* const* d_in, const int* in_sizes, int n_in,
                              void* d_out, int out_size) {
    const int*   x   = (const int*)  d_in[0];
    const float* emb = (const float*)d_in[1];
    const float* dww = (const float*)d_in[2];
    const float* dwb = (const float*)d_in[3];
    const float* pww = (const float*)d_in[4];
    const float* pwb = (const float*)d_in[5];
    const float* sw  = (const float*)d_in[6];
    const float* sb  = (const float*)d_in[7];
    float* out = (float*)d_out;

    cudaFuncSetAttribute(k_gemm_mma, cudaFuncAttributeMaxDynamicSharedMemorySize, GEMM_SMEM);

    k_conv<<<dim3(NN / 8, BQ), 128>>>(x, emb, dww, dwb, pww);
    k_gemm_mma<<<dim3(128, 4), 256, GEMM_SMEM>>>(pwb, sw);
    k_scores<<<(NROWS + 255) / 256, 256>>>(sb);
    k_attn_part<<<dim3((HQ + 127) / 128, BQ, NSPLIT), 128>>>();
    k_out<<<dim3(1024, BQ), 128>>>(out);
}

// round 12
// speedup vs baseline: 1.1268x; 1.0295x over previous
#include <cuda_runtime.h>
#include <cuda_bf16.h>
#include <cstdint>

#define BQ 4
#define NN 4096
#define DM 512
#define LP 4104   // ceil(4096/12)*12
#define NROWS (BQ*LP)
#define NSPLIT 24
#define LQS (LP/NSPLIT)   // 171 keys per split
#define HQ (LP/2)         // 2052

// ---------------- scratch (device globals) ----------------
__device__ __nv_bfloat16 g_Yh[(size_t)BQ*NN*DM];   // conv output hi
__device__ __nv_bfloat16 g_Yl[(size_t)BQ*NN*DM];   // conv output lo
__device__ __nv_bfloat16 g_Wh[DM*DM];              // pw_w hi
__device__ __nv_bfloat16 g_Wl[DM*DM];              // pw_w lo
__device__ float g_Y2[(size_t)BQ*LP*DM];           // pointwise output
__device__ float g_T [NROWS];                      // per-position score dot (atomic)
__device__ float g_S [NROWS*4];                    // softmaxed block scores
__device__ float4 g_Pa[NSPLIT][NROWS];             // attention partial numerators

// ---------------- f32x2 packed helpers ----------------
__device__ __forceinline__ unsigned long long mul2(unsigned long long a, unsigned long long b) {
    unsigned long long d;
    asm("mul.rn.f32x2 %0, %1, %2;" : "=l"(d) : "l"(a), "l"(b));
    return d;
}
__device__ __forceinline__ unsigned long long fma2(unsigned long long a, unsigned long long b,
                                                   unsigned long long c) {
    unsigned long long d;
    asm("fma.rn.f32x2 %0, %1, %2, %3;" : "=l"(d) : "l"(a), "l"(b), "l"(c));
    return d;
}
__device__ __forceinline__ unsigned long long pack2(float lo, float hi) {
    unsigned long long d;
    asm("mov.b64 %0, {%1, %2};" : "=l"(d) : "f"(lo), "f"(hi));
    return d;
}
__device__ __forceinline__ void unpack2(unsigned long long v, float& lo, float& hi) {
    asm("mov.b64 {%0, %1}, %2;" : "=f"(lo), "=f"(hi) : "l"(v));
}

// ---------------- conv (+ fused prep: W split, T zero, Y2 pad zero) ----------------
__global__ void __launch_bounds__(128) k_conv(const int* __restrict__ x,
                                              const float* __restrict__ emb,
                                              const float* __restrict__ dww,
                                              const float* __restrict__ dwb,
                                              const float* __restrict__ W) {
    // fused prep: 2048 blocks * 128 threads = 262144 = DM*DM exactly
    int gidx = (blockIdx.y * gridDim.x + blockIdx.x) * 128 + threadIdx.x;
    {
        float w = W[gidx];
        __nv_bfloat16 h = __float2bfloat16(w);
        g_Wh[gidx] = h;
        g_Wl[gidx] = __float2bfloat16(w - __bfloat162float(h));
    }
    if (gidx < NROWS) g_T[gidx] = 0.0f;
    if (gidx < BQ * 8 * DM) {
        int bb = gidx / (8 * DM);
        int r = gidx % (8 * DM);
        g_Y2[((size_t)bb * LP + NN + r / DM) * DM + (r % DM)] = 0.0f;
    }

    __shared__ float sE[11][DM];     // rows t0 .. t0+10 (22.5 KB)
    int t0 = blockIdx.x * 8;
    int b = blockIdx.y;
    int tid = threadIdx.x;

    for (int v = tid; v < 11 * 128; v += 128) {
        int r = v >> 7;
        int c4 = (v & 127) * 4;
        int t = t0 + r;
        float4 e = {0.f, 0.f, 0.f, 0.f};
        if (t < NN) {
            int id = x[b * NN + t];
            e = *(const float4*)(emb + (size_t)id * DM + c4);
        }
        *(float4*)(&sE[r][c4]) = e;
    }
    __syncthreads();

    int d0 = tid * 4;
    float w[4][4];
#pragma unroll
    for (int j = 0; j < 4; j++) {
        float4 wv = *(const float4*)(dww + (d0 + j) * 4);
        w[j][0] = wv.x; w[j][1] = wv.y; w[j][2] = wv.z; w[j][3] = wv.w;
    }
    float4 bb = *(const float4*)(dwb + d0);

#pragma unroll
    for (int tok = 0; tok < 8; tok++) {
        float acc[4] = {bb.x, bb.y, bb.z, bb.w};
#pragma unroll
        for (int k = 0; k < 4; k++) {
            float4 e = *(const float4*)(&sE[tok + k][d0]);
            acc[0] += e.x * w[0][k];
            acc[1] += e.y * w[1][k];
            acc[2] += e.z * w[2][k];
            acc[3] += e.w * w[3][k];
        }
        size_t base = ((size_t)(b * NN + t0 + tok)) * DM + d0;
        __nv_bfloat16 h[4], l[4];
#pragma unroll
        for (int j = 0; j < 4; j++) {
            h[j] = __float2bfloat16(acc[j]);
            l[j] = __float2bfloat16(acc[j] - __bfloat162float(h[j]));
        }
        __nv_bfloat162* ph = (__nv_bfloat162*)(g_Yh + base);
        __nv_bfloat162* pl = (__nv_bfloat162*)(g_Yl + base);
        ph[0] = __halves2bfloat162(h[0], h[1]);
        ph[1] = __halves2bfloat162(h[2], h[3]);
        pl[0] = __halves2bfloat162(l[0], l[1]);
        pl[1] = __halves2bfloat162(l[2], l[3]);
    }
}

// ---------------- HMMA GEMM: Y2 = Y @ W^T + bias, bf16x3, cp.async 3-stage ----------------
#define TILE_B 8192          // 128 rows * 64 B
#define STAGE_B (4*TILE_B)   // Ah, Al, Bh, Bl = 32768
#define GEMM_SMEM (3*STAGE_B)  // 98304

__device__ __forceinline__ uint32_t swz(uint32_t row, uint32_t chunk) {
    return row * 64 + ((chunk ^ ((row >> 1) & 3)) << 4);
}
__device__ __forceinline__ void ldsm4(uint32_t* r, uint32_t addr) {
    asm volatile("ldmatrix.sync.aligned.m8n8.x4.shared.b16 {%0,%1,%2,%3}, [%4];"
                 : "=r"(r[0]), "=r"(r[1]), "=r"(r[2]), "=r"(r[3]) : "r"(addr));
}
__device__ __forceinline__ void mma16816(float* c, const uint32_t* a, const uint32_t* b) {
    asm volatile(
        "mma.sync.aligned.m16n8k16.row.col.f32.bf16.bf16.f32 "
        "{%0,%1,%2,%3}, {%4,%5,%6,%7}, {%8,%9}, {%0,%1,%2,%3};"
        : "+f"(c[0]), "+f"(c[1]), "+f"(c[2]), "+f"(c[3])
        : "r"(a[0]), "r"(a[1]), "r"(a[2]), "r"(a[3]), "r"(b[0]), "r"(b[1]));
}
__device__ __forceinline__ void cpa16(uint32_t dst, const void* src) {
    asm volatile("cp.async.cg.shared.global [%0], [%1], 16;" :: "r"(dst), "l"(src));
}

__global__ void __launch_bounds__(256, 2) k_gemm_mma(const float* __restrict__ bias,
                                                     const float* __restrict__ sw) {
    extern __shared__ char sm[];
    uint32_t smu = (uint32_t)__cvta_generic_to_shared(sm);

    int tid = threadIdx.x, wid = tid >> 5, lane = tid & 31;
    int warp_m = wid & 1;
    int warp_n = wid >> 1;
    int mtile = blockIdx.x;
    int bn = blockIdx.y;

    const __nv_bfloat16* gA[2] = {g_Yh + (size_t)mtile * 128 * DM,
                                  g_Yl + (size_t)mtile * 128 * DM};
    const __nv_bfloat16* gB[2] = {g_Wh + (size_t)bn * 128 * DM,
                                  g_Wl + (size_t)bn * 128 * DM};

    int r0 = tid >> 2, cc0 = tid & 3;
    int r1 = r0 + 64;
    uint32_t so0 = swz(r0, cc0);
    uint32_t so1 = swz(r1, cc0);

    auto load_stage = [&](int kc, int stage) {
        uint32_t base = smu + stage * STAGE_B;
        size_t go0 = (size_t)r0 * DM + kc * 32 + cc0 * 8;
        size_t go1 = (size_t)r1 * DM + kc * 32 + cc0 * 8;
#pragma unroll
        for (int p = 0; p < 2; p++) {
            cpa16(base + p * TILE_B + so0, gA[p] + go0);
            cpa16(base + p * TILE_B + so1, gA[p] + go1);
            cpa16(base + (2 + p) * TILE_B + so0, gB[p] + go0);
            cpa16(base + (2 + p) * TILE_B + so1, gB[p] + go1);
        }
        asm volatile("cp.async.commit_group;");
    };

    float c[4][4][4];
#pragma unroll
    for (int mt = 0; mt < 4; mt++)
#pragma unroll
        for (int nt = 0; nt < 4; nt++)
#pragma unroll
            for (int e = 0; e < 4; e++) c[mt][nt][e] = 0.0f;

    int lr = lane & 7, g = lane >> 3;
    int a_row = (g & 1) * 8 + lr;
    int a_kc8 = (g >> 1);
    int b_nrw = (g >> 1) * 8 + lr;
    int b_kc8 = (g & 1);

    load_stage(0, 0);
    load_stage(1, 1);

    for (int kc = 0; kc < 16; kc++) {
        if (kc + 1 < 16) asm volatile("cp.async.wait_group 1;");
        else             asm volatile("cp.async.wait_group 0;");
        __syncthreads();
        if (kc + 2 < 16) load_stage(kc + 2, (kc + 2) % 3);

        uint32_t sAh = smu + (kc % 3) * STAGE_B;
        uint32_t sAl = sAh + TILE_B;
        uint32_t sBh = sAh + 2 * TILE_B;
        uint32_t sBl = sAh + 3 * TILE_B;

#pragma unroll
        for (int ks = 0; ks < 2; ks++) {
            uint32_t bh[8], bl[8], a[4][4];
#pragma unroll
            for (int hh = 0; hh < 2; hh++) {
                uint32_t row = warp_n * 32 + hh * 16 + b_nrw;
                uint32_t off = swz(row, 2 * ks + b_kc8);
                ldsm4(bh + hh * 4, sBh + off);
                ldsm4(bl + hh * 4, sBl + off);
            }
#pragma unroll
            for (int mt = 0; mt < 4; mt++) {
                uint32_t row = warp_m * 64 + mt * 16 + a_row;
                uint32_t off = swz(row, 2 * ks + a_kc8);
                ldsm4(a[mt], sAh + off);
            }
#pragma unroll
            for (int mt = 0; mt < 4; mt++)
#pragma unroll
                for (int nt = 0; nt < 4; nt++) {
                    int bi = (nt >> 1) * 4 + (nt & 1) * 2;
                    uint32_t b0[2] = {bh[bi], bh[bi + 1]};
                    mma16816(c[mt][nt], a[mt], b0);
                    uint32_t b1[2] = {bl[bi], bl[bi + 1]};
                    mma16816(c[mt][nt], a[mt], b1);
                }
#pragma unroll
            for (int mt = 0; mt < 4; mt++) {
                uint32_t row = warp_m * 64 + mt * 16 + a_row;
                uint32_t off = swz(row, 2 * ks + a_kc8);
                ldsm4(a[mt], sAl + off);
            }
#pragma unroll
            for (int mt = 0; mt < 4; mt++)
#pragma unroll
                for (int nt = 0; nt < 4; nt++) {
                    int bi = (nt >> 1) * 4 + (nt & 1) * 2;
                    uint32_t b0[2] = {bh[bi], bh[bi + 1]};
                    mma16816(c[mt][nt], a[mt], b0);
                }
        }
    }

    float tp[4][2];
#pragma unroll
    for (int mt = 0; mt < 4; mt++) { tp[mt][0] = 0.0f; tp[mt][1] = 0.0f; }

#pragma unroll
    for (int mt = 0; mt < 4; mt++) {
        int row0 = mtile * 128 + warp_m * 64 + mt * 16 + (lane >> 2);
        int row1 = row0 + 8;
        int b0i = row0 >> 12, l0i = row0 & 4095;
        int b1i = row1 >> 12, l1i = row1 & 4095;
        float* o0 = g_Y2 + ((size_t)b0i * LP + l0i) * DM;
        float* o1 = g_Y2 + ((size_t)b1i * LP + l1i) * DM;
#pragma unroll
        for (int nt = 0; nt < 4; nt++) {
            int col = bn * 128 + warp_n * 32 + nt * 8 + 2 * (lane & 3);
            float bi0 = bias[col], bi1 = bias[col + 1];
            float s0 = sw[col], s1 = sw[col + 1];
            float v00 = c[mt][nt][0] + bi0, v01 = c[mt][nt][1] + bi1;
            float v10 = c[mt][nt][2] + bi0, v11 = c[mt][nt][3] + bi1;
            tp[mt][0] += v00 * s0 + v01 * s1;
            tp[mt][1] += v10 * s0 + v11 * s1;
            float2 w0 = {v00, v01}, w1 = {v10, v11};
            *(float2*)(o0 + col) = w0;
            *(float2*)(o1 + col) = w1;
        }
    }
#pragma unroll
    for (int mt = 0; mt < 4; mt++) {
#pragma unroll
        for (int rs = 0; rs < 2; rs++) {
            float r = tp[mt][rs];
            r += __shfl_xor_sync(0xffffffff, r, 1);
            r += __shfl_xor_sync(0xffffffff, r, 2);
            if ((lane & 3) == 0) {
                int row = mtile * 128 + warp_m * 64 + mt * 16 + rs * 8 + (lane >> 2);
                int bb = row >> 12, ll = row & 4095;
                atomicAdd(&g_T[bb * LP + ll], r);
            }
        }
    }
}

// ---------------- block means of T + softmax over k ----------------
__global__ void __launch_bounds__(256) k_scores(const float* __restrict__ sb) {
    int idx = blockIdx.x * blockDim.x + threadIdx.x;
    if (idx >= NROWS) return;
    int b = idx / LP, l = idx % LP;
    const float* Tb = g_T + (size_t)b * LP;
    float v[4];
    v[0] = Tb[l];
    { int j = l & ~1;      v[1] = (Tb[j] + Tb[j + 1]) * 0.5f; }
    { int j = (l / 3) * 3; v[2] = (Tb[j] + Tb[j + 1] + Tb[j + 2]) * (1.0f / 3.0f); }
    { int j = l & ~3;      v[3] = (Tb[j] + Tb[j + 1] + Tb[j + 2] + Tb[j + 3]) * 0.25f; }
    float mx = v[0];
#pragma unroll
    for (int k = 1; k < 4; k++) mx = fmaxf(mx, v[k]);
    float e[4], z = 0.0f;
#pragma unroll
    for (int k = 0; k < 4; k++) { e[k] = __expf(v[k] - mx); z += e[k]; }
    float inv = 1.0f / z;
    float4 o = {e[0] * inv, e[1] * inv, e[2] * inv, e[3] * inv};
    *(float4*)(g_S + (size_t)idx * 4) = o;
}

// ---------------- score attention, 24-way key split, 2 queries/thread, f32x2 ----------------
// z is NOT accumulated: keys are softmaxed (components sum to 1), so
// z = sum_j e_j = sum of the 4 components of the numerator.
__global__ void __launch_bounds__(128) k_attn_part() {
    __shared__ float4 sS[LQS];   // 171 keys = 2.7 KB
    int b = blockIdx.y, sp = blockIdx.z;
    const float4* Sb = (const float4*)(g_S + ((size_t)b * LP + sp * LQS) * 4);
    for (int j = threadIdx.x; j < LQS; j += 128) sS[j] = Sb[j];
    __syncthreads();

    int i0 = blockIdx.x * 128 + threadIdx.x;
    if (i0 >= HQ) return;
    int i1 = i0 + HQ;

    const float L2E = 1.4426950408889634f;
    float4 q0 = *(const float4*)(g_S + ((size_t)b * LP + i0) * 4);
    float4 q1 = *(const float4*)(g_S + ((size_t)b * LP + i1) * 4);
    unsigned long long q0a = pack2(q0.x * L2E, q0.y * L2E);
    unsigned long long q0b = pack2(q0.z * L2E, q0.w * L2E);
    unsigned long long q1a = pack2(q1.x * L2E, q1.y * L2E);
    unsigned long long q1b = pack2(q1.z * L2E, q1.w * L2E);

    unsigned long long A0a = 0, A0b = 0, A1a = 0, A1b = 0;

    const ulonglong2* sSv = (const ulonglong2*)sS;
#pragma unroll 3
    for (int j = 0; j < LQS; j++) {
        ulonglong2 sv = sSv[j];
        unsigned long long d0p = fma2(q0b, sv.y, mul2(q0a, sv.x));
        float d0l, d0h; unpack2(d0p, d0l, d0h);
        float e0;
        asm("ex2.approx.f32 %0, %1;" : "=f"(e0) : "f"(d0l + d0h));
        unsigned long long e0p = pack2(e0, e0);
        A0a = fma2(e0p, sv.x, A0a);
        A0b = fma2(e0p, sv.y, A0b);
        unsigned long long d1p = fma2(q1b, sv.y, mul2(q1a, sv.x));
        float d1l, d1h; unpack2(d1p, d1l, d1h);
        float e1;
        asm("ex2.approx.f32 %0, %1;" : "=f"(e1) : "f"(d1l + d1h));
        unsigned long long e1p = pack2(e1, e1);
        A1a = fma2(e1p, sv.x, A1a);
        A1b = fma2(e1p, sv.y, A1b);
    }

    float4 r0, r1;
    unpack2(A0a, r0.x, r0.y); unpack2(A0b, r0.z, r0.w);
    unpack2(A1a, r1.x, r1.y); unpack2(A1b, r1.z, r1.w);
    int row0 = b * LP + i0, row1 = b * LP + i1;
    g_Pa[sp][row0] = r0;
    g_Pa[sp][row1] = r1;
}

// ---------------- output: split-reduce + one-thread weight build + pooled store ----------
__global__ void __launch_bounds__(128) k_out(float* __restrict__ out) {
    __shared__ float4 s2s[4];
    __shared__ float ws[8];
    int g = blockIdx.x;
    int b = blockIdx.y;
    int base = 4 * g - 2;
    int tid = threadIdx.x;

    if (tid < 4) {
        int row = b * LP + 4 * g + tid;
        float4 a = make_float4(0.0f, 0.0f, 0.0f, 0.0f);
#pragma unroll
        for (int s = 0; s < NSPLIT; s++) {
            float4 p = g_Pa[s][row];
            a.x += p.x; a.y += p.y; a.z += p.z; a.w += p.w;
        }
        float z = a.x + a.y + a.z + a.w;   // keys sum to 1 -> denominator
        float inv = 1.0f / z;
        s2s[tid] = make_float4(a.x * inv, a.y * inv, a.z * inv, a.w * inv);
    }
    __syncthreads();

    if (tid == 0) {
        float w[8];
#pragma unroll
        for (int r = 0; r < 8; r++) w[r] = 0.0f;
#pragma unroll
        for (int lo = 0; lo < 4; lo++) {
            int l = 4 * g + lo;
            float4 s2 = s2s[lo];
            w[l - base] += s2.x * 0.25f;
            { int j0 = l & ~1;      float c = s2.y * (0.25f * 0.5f);
              w[j0 - base] += c; w[j0 + 1 - base] += c; }
            { int j0 = (l / 3) * 3; float c = s2.z * (0.25f / 3.0f);
              w[j0 - base] += c; w[j0 + 1 - base] += c; w[j0 + 2 - base] += c; }
            { int j0 = l & ~3;      float c = s2.w * (0.25f * 0.25f);
              w[j0 - base] += c; w[j0 + 1 - base] += c;
              w[j0 + 2 - base] += c; w[j0 + 3 - base] += c; }
        }
#pragma unroll
        for (int r = 0; r < 8; r++) ws[r] = w[r];
    }
    __syncthreads();

    int d = tid * 4;
    const float* Yb = g_Y2 + ((size_t)b * LP + base) * DM + d;
    float4 acc = {0.0f, 0.0f, 0.0f, 0.0f};
#pragma unroll
    for (int r = 0; r < 8; r++) {
        int row = base + r;
        float wr = ws[r];
        if (row >= 0 && wr != 0.0f) {
            float4 v = *(const float4*)(Yb + (size_t)r * DM);
            acc.x += wr * v.x; acc.y += wr * v.y;
            acc.z += wr * v.z; acc.w += wr * v.w;
        }
    }
    *(float4*)(out + ((size_t)(b * 1024 + g)) * DM + d) = acc;
}

// ---------------- launcher ----------------
extern "C" void kernel_launch(void* const* d_in, const int* in_sizes, int n_in,
                              void* d_out, int out_size) {
    const int*   x   = (const int*)  d_in[0];
    const float* emb = (const float*)d_in[1];
    const float* dww = (const float*)d_in[2];
    const float* dwb = (const float*)d_in[3];
    const float* pww = (const float*)d_in[4];
    const float* pwb = (const float*)d_in[5];
    const float* sw  = (const float*)d_in[6];
    const float* sb  = (const float*)d_in[7];
    float* out = (float*)d_out;

    cudaFuncSetAttribute(k_gemm_mma, cudaFuncAttributeMaxDynamicSharedMemorySize, GEMM_SMEM);

    k_conv<<<dim3(NN / 8, BQ), 128>>>(x, emb, dww, dwb, pww);
    k_gemm_mma<<<dim3(128, 4), 256, GEMM_SMEM>>>(pwb, sw);
    k_scores<<<(NROWS + 255) / 256, 256>>>(sb);
    k_attn_part<<<dim3((HQ + 127) / 128, BQ, NSPLIT), 128>>>();
    k_out<<<dim3(1024, BQ), 128>>>(out);
}